// round 2
// baseline (speedup 1.0000x reference)
#include <cuda_runtime.h>
#include <cstdint>

typedef unsigned long long ull;

#define B_   1024
#define T_   1024
#define H_   128
#define C_   6
#define BPC  8            // batches per CTA
#define NCTA (B_/BPC)     // 128

// ---------------- packed transposed weights (device globals; no allocs) ----
__device__ float4 g_packA[H_*H_];   // [k][j] = (whh_r[j][k], whh_z[j][k], whh_n[j][k], w1[j][k])
__device__ float  g_wu1T[H_*64];    // [k][j] = wu1[j][k], j<64
__device__ float4 g_packI[12*H_];   // [k][j] = (wih_r[j][k], wih_z[j][k], wih_n[j][k], 0)

// ---------------- f32x2 helpers (Blackwell packed fp32) --------------------
__device__ __forceinline__ ull pk2(float a, float b){
    ull r; asm("mov.b64 %0, {%1,%2};" : "=l"(r) : "f"(a), "f"(b)); return r;
}
__device__ __forceinline__ void fma2(ull& d, ull a, ull b){
    asm("fma.rn.f32x2 %0, %1, %2, %3;" : "=l"(d) : "l"(a), "l"(b), "l"(d));
}
__device__ __forceinline__ float2 up2(ull v){
    float2 r; asm("mov.b64 {%0,%1}, %2;" : "=f"(r.x), "=f"(r.y) : "l"(v)); return r;
}

__device__ __forceinline__ float sigf(float x){
    return __fdividef(1.f, 1.f + __expf(-x));
}
__device__ __forceinline__ float tanhfast(float x){
    float e = __expf(-2.f * fabsf(x));
    float t = __fdividef(1.f - e, 1.f + e);
    return copysignf(t, x);
}

// ---------------- weight pack pre-pass -------------------------------------
__global__ void pack_kernel(const float* __restrict__ w_ih, const float* __restrict__ w_hh,
                            const float* __restrict__ w1,   const float* __restrict__ wu1){
    int idx = blockIdx.x * blockDim.x + threadIdx.x;   // 0..16383
    int k = idx >> 7, j = idx & 127;
    g_packA[idx] = make_float4(w_hh[j*H_ + k], w_hh[(j+H_)*H_ + k],
                               w_hh[(j+2*H_)*H_ + k], w1[j*H_ + k]);
    if (j < 64)  g_wu1T[k*64 + j] = wu1[j*H_ + k];
    if (k < 12)  g_packI[k*H_ + j] = make_float4(w_ih[j*12 + k], w_ih[(j+H_)*12 + k],
                                                 w_ih[(j+2*H_)*12 + k], 0.f);
}

// ---------------- dynamic smem layout (floats) ------------------------------
#define OFF_H     0        // sh_h  [128][8]  h(t-1) undecayed
#define OFF_HD    1024     // sh_hd [128][8]  gamma_h * h(t-1)
#define OFF_GIN   2048     // sh_gin[12][8]
#define OFF_DT    2144     // sh_dt [8]
#define OFF_HID1  2152     // sh_hid1[8][128]
#define OFF_HIDU  3176     // sh_hidu[8][64]
#define OFF_WU1   3688     // s_wu1 [128][64]
#define OFF_PI    11880    // s_pI  [12][128] float4
#define SMEM_FLOATS (OFF_PI + 12*H_*4)
#define SMEM_BYTES  (SMEM_FLOATS * 4)   // 72096

__global__ void __launch_bounds__(128, 1) grud_kernel(
    const float* __restrict__ x,
    const float* __restrict__ x_mean,
    const float* __restrict__ dxw, const float* __restrict__ dxb,
    const float* __restrict__ dhw, const float* __restrict__ dhb,
    const float* __restrict__ b_ih, const float* __restrict__ b_hh,
    const float* __restrict__ b1,
    const float* __restrict__ w2,  const float* __restrict__ b2,
    const float* __restrict__ bu1,
    const float* __restrict__ wu2, const float* __restrict__ bu2,
    float* __restrict__ out)
{
    extern __shared__ float smem[];
    float*  sh_h   = smem + OFF_H;      // [k*8 + b]
    float*  sh_hd  = smem + OFF_HD;
    float*  sh_gin = smem + OFF_GIN;    // [k*8 + b]
    float*  sh_dt  = smem + OFF_DT;
    float*  sh_hid1= smem + OFF_HID1;   // [b*128 + j]
    float*  sh_hidu= smem + OFF_HIDU;   // [b*64 + j]
    float*  s_wu1  = smem + OFF_WU1;    // [k*64 + j]
    float4* s_pI   = (float4*)(smem + OFF_PI);  // [k*128 + j]

    const int tid = threadIdx.x;
    const int j   = tid;
    const int b0  = blockIdx.x * BPC;

    // stage small weights into shared (once)
    for (int i = tid; i < H_*64; i += 128) s_wu1[i] = g_wu1T[i];
    for (int i = tid; i < 12*H_; i += 128) s_pI[i]  = g_packI[i];

    // per-hidden-unit constants
    const float bihr = b_ih[j], bihz = b_ih[H_ + j], bihn = b_ih[2*H_ + j];
    const float bhhr = b_hh[j], bhhz = b_hh[H_ + j], bhhn = b_hh[2*H_ + j];
    const float b1j  = b1[j];
    const float bu1j = (j < 64) ? bu1[j] : 0.f;
    const float dhwj = dhw[j],  dhbj = dhb[j];

    // phase-A (imputation) thread constants: tid<48 -> (batch ab, feature ac)
    const int ab = tid / 6, ac = tid - ab * 6;
    float xm = 0.f, axw = 0.f, axb = 0.f, b2c = 0.f;
    if (tid < 48) { xm = x_mean[ac]; axw = dxw[ac]; axb = dxb[ac]; b2c = b2[ac]; }
    // unc reducer constants: tid in [64,112) -> (ub, uc)
    const int ui = tid - 64;
    const int ub = ui / 6, uc = ui - ub * 6;
    float bu2c = 0.f;
    if (tid >= 64 && tid < 112) bu2c = bu2[uc];

    float running = 0.f, xlast = 0.f;
    float h_reg[BPC];
    #pragma unroll
    for (int b = 0; b < BPC; b++) h_reg[b] = 0.f;

    __syncthreads();   // staged weights ready

    for (int t = 0; t <= T_; ++t) {
        // ---------------- Phase A: impute inputs for step t -----------------
        if (t < T_ && tid < 48) {
            const float* xp = x + ((size_t)(b0 + ab) * T_ + t) * 13;
            float xv  = xp[ac];
            float mm  = xp[6 + ac];
            float dtv = xp[12];
            bool obs = (mm > 0.5f);
            running = obs ? 0.f : (running + dtv);
            float gx = __expf(-fmaxf(running * axw + axb, 0.f));
            xlast = obs ? xv : xlast;
            float xhat = mm * xv + (1.f - mm) * (gx * xlast + (1.f - gx) * xm);
            sh_gin[ac * 8 + ab]       = xhat;
            sh_gin[(6 + ac) * 8 + ab] = mm;
            if (ac == 0) sh_dt[ab] = dtv;
        }
        __syncthreads();

        // ---------------- Phase B: decay h, publish to shared ---------------
        float hdec[BPC];
        #pragma unroll
        for (int b = 0; b < BPC; b++) {
            float g = __expf(-fmaxf(sh_dt[b] * dhwj + dhbj, 0.f));
            hdec[b] = h_reg[b] * g;
        }
        *(float4*)(sh_h  + j*8)     = make_float4(h_reg[0], h_reg[1], h_reg[2], h_reg[3]);
        *(float4*)(sh_h  + j*8 + 4) = make_float4(h_reg[4], h_reg[5], h_reg[6], h_reg[7]);
        *(float4*)(sh_hd + j*8)     = make_float4(hdec[0], hdec[1], hdec[2], hdec[3]);
        *(float4*)(sh_hd + j*8 + 4) = make_float4(hdec[4], hdec[5], hdec[6], hdec[7]);
        __syncthreads();

        // ---------------- Phase C: fused GEMV loops -------------------------
        ull aR[4], aZ[4], aGN[4], aIN[4], aP[4], aU[4];
        #pragma unroll
        for (int p = 0; p < 4; p++) { aR[p]=0; aZ[p]=0; aGN[p]=0; aIN[p]=0; aP[p]=0; aU[p]=0; }

        // input-to-hidden: gi over gru_in[12]
        #pragma unroll
        for (int k = 0; k < 12; k++) {
            float4 wi = s_pI[k*H_ + j];
            ull wr = pk2(wi.x, wi.x), wz = pk2(wi.y, wi.y), wn = pk2(wi.z, wi.z);
            ulonglong2 gA = *(const ulonglong2*)(sh_gin + k*8);
            ulonglong2 gB = *(const ulonglong2*)(sh_gin + k*8 + 4);
            fma2(aR[0], gA.x, wr); fma2(aR[1], gA.y, wr); fma2(aR[2], gB.x, wr); fma2(aR[3], gB.y, wr);
            fma2(aZ[0], gA.x, wz); fma2(aZ[1], gA.y, wz); fma2(aZ[2], gB.x, wz); fma2(aZ[3], gB.y, wz);
            fma2(aIN[0],gA.x, wn); fma2(aIN[1],gA.y, wn); fma2(aIN[2],gB.x, wn); fma2(aIN[3],gB.y, wn);
        }

        // hidden-to-hidden (on decayed h) + head layer-1 (on undecayed h(t-1))
        #pragma unroll 4
        for (int k = 0; k < H_; k++) {
            float4 wA = g_packA[k*H_ + j];
            ulonglong2 dA = *(const ulonglong2*)(sh_hd + k*8);
            ulonglong2 dB = *(const ulonglong2*)(sh_hd + k*8 + 4);
            ulonglong2 hA = *(const ulonglong2*)(sh_h  + k*8);
            ulonglong2 hB = *(const ulonglong2*)(sh_h  + k*8 + 4);
            ull wr = pk2(wA.x, wA.x), wz = pk2(wA.y, wA.y), wn = pk2(wA.z, wA.z), wp = pk2(wA.w, wA.w);
            fma2(aR[0], dA.x, wr); fma2(aR[1], dA.y, wr); fma2(aR[2], dB.x, wr); fma2(aR[3], dB.y, wr);
            fma2(aZ[0], dA.x, wz); fma2(aZ[1], dA.y, wz); fma2(aZ[2], dB.x, wz); fma2(aZ[3], dB.y, wz);
            fma2(aGN[0],dA.x, wn); fma2(aGN[1],dA.y, wn); fma2(aGN[2],dB.x, wn); fma2(aGN[3],dB.y, wn);
            fma2(aP[0], hA.x, wp); fma2(aP[1], hA.y, wp); fma2(aP[2], hB.x, wp); fma2(aP[3], hB.y, wp);
            if (j < 64) {
                float wu = s_wu1[k*64 + j];
                ull wu2p = pk2(wu, wu);
                fma2(aU[0], hA.x, wu2p); fma2(aU[1], hA.y, wu2p);
                fma2(aU[2], hB.x, wu2p); fma2(aU[3], hB.y, wu2p);
            }
        }

        // ---------------- Phase D: gates + head activations -----------------
        float fR[8], fZ[8], fGN[8], fIN[8], fP[8], fU[8];
        #pragma unroll
        for (int p = 0; p < 4; p++) {
            float2 v;
            v = up2(aR[p]);  fR[2*p]  = v.x; fR[2*p+1]  = v.y;
            v = up2(aZ[p]);  fZ[2*p]  = v.x; fZ[2*p+1]  = v.y;
            v = up2(aGN[p]); fGN[2*p] = v.x; fGN[2*p+1] = v.y;
            v = up2(aIN[p]); fIN[2*p] = v.x; fIN[2*p+1] = v.y;
            v = up2(aP[p]);  fP[2*p]  = v.x; fP[2*p+1]  = v.y;
            v = up2(aU[p]);  fU[2*p]  = v.x; fU[2*p+1]  = v.y;
        }
        #pragma unroll
        for (int b = 0; b < BPC; b++) {
            float r = sigf(fR[b] + bihr + bhhr);
            float z = sigf(fZ[b] + bihz + bhhz);
            float n = tanhfast(fIN[b] + bihn + r * (fGN[b] + bhhn));
            h_reg[b] = n + z * (hdec[b] - n);            // (1-z)*n + z*h_dec
            // heads for step t-1 (computed from sh_h = h(t-1))
            sh_hid1[b*H_ + j] = fmaxf(fP[b] + b1j, 0.f);
            if (j < 64) sh_hidu[b*64 + j] = fmaxf(fU[b] + bu1j, 0.f);
        }
        __syncthreads();

        // ---------------- Reduction: head layer-2, write outputs t-1 --------
        if (t >= 1) {
            if (tid < 48) {
                float acc = b2c;
                const float* wrow = w2 + ac * H_;
                #pragma unroll 8
                for (int k = 0; k < H_; k += 4) {
                    float4 hh = *(const float4*)(sh_hid1 + ab*H_ + k);
                    float4 ww = *(const float4*)(wrow + k);
                    acc += hh.x*ww.x + hh.y*ww.y + hh.z*ww.z + hh.w*ww.w;
                }
                out[((size_t)(b0 + ab) * T_ + (t - 1)) * C_ + ac] = acc;
            } else if (tid >= 64 && tid < 112) {
                float acc = bu2c;
                const float* wrow = wu2 + uc * 64;
                #pragma unroll 8
                for (int k = 0; k < 64; k += 4) {
                    float4 hh = *(const float4*)(sh_hidu + ub*64 + k);
                    float4 ww = *(const float4*)(wrow + k);
                    acc += hh.x*ww.x + hh.y*ww.y + hh.z*ww.z + hh.w*ww.w;
                }
                // softplus (numerically stable, matches jax.nn.softplus)
                float sp = fmaxf(acc, 0.f) + log1pf(__expf(-fabsf(acc)));
                out[(size_t)B_*T_*C_ + ((size_t)(b0 + ub) * T_ + (t - 1)) * C_ + uc] = sp;
            }
        }
        // next iteration's Phase-A writes (sh_gin/sh_dt) don't collide with
        // this reduction (different arrays); Phase-B overwrite of sh_h/sh_hd
        // is fenced by the Phase-A __syncthreads.
    }
}

extern "C" void kernel_launch(void* const* d_in, const int* in_sizes, int n_in,
                              void* d_out, int out_size) {
    const float* x      = (const float*)d_in[0];
    const float* x_mean = (const float*)d_in[1];
    const float* dxw    = (const float*)d_in[2];
    const float* dxb    = (const float*)d_in[3];
    const float* dhw    = (const float*)d_in[4];
    const float* dhb    = (const float*)d_in[5];
    const float* w_ih   = (const float*)d_in[6];
    const float* w_hh   = (const float*)d_in[7];
    const float* b_ih   = (const float*)d_in[8];
    const float* b_hh   = (const float*)d_in[9];
    const float* w1     = (const float*)d_in[10];
    const float* b1     = (const float*)d_in[11];
    const float* w2     = (const float*)d_in[12];
    const float* b2     = (const float*)d_in[13];
    const float* wu1    = (const float*)d_in[14];
    const float* bu1    = (const float*)d_in[15];
    const float* wu2    = (const float*)d_in[16];
    const float* bu2    = (const float*)d_in[17];
    float* out = (float*)d_out;

    // No static guards (harness forbids them); this call is idempotent and is
    // not a stream-captured operation.
    cudaFuncSetAttribute(grud_kernel, cudaFuncAttributeMaxDynamicSharedMemorySize, SMEM_BYTES);

    pack_kernel<<<NCTA, 128>>>(w_ih, w_hh, w1, wu1);
    grud_kernel<<<NCTA, 128, SMEM_BYTES>>>(x, x_mean, dxw, dxb, dhw, dhb,
                                           b_ih, b_hh, b1, w2, b2, bu1, wu2, bu2, out);
}

// round 3
// speedup vs baseline: 1.2132x; 1.2132x over previous
#include <cuda_runtime.h>
#include <cstdint>

typedef unsigned long long ull;

#define B_   1024
#define T_   1024
#define H_   128
#define C_   6
#define BPC  8            // batches per CTA
#define NCTA (B_/BPC)     // 128
#define KC   48           // k-rows of packA cached in smem

// ---------------- packed transposed weights (device globals; no allocs) ----
__device__ float4 g_packA[H_*H_];   // [k][j] = (whh_r[j][k], whh_z[j][k], whh_n[j][k], w1[j][k])
__device__ float  g_wu1T[H_*64];    // [k][j] = wu1[j][k], j<64
__device__ float4 g_packI[12*H_];   // [k][j] = (wih_r[j][k], wih_z[j][k], wih_n[j][k], 0)

// ---------------- f32x2 helpers (Blackwell packed fp32) --------------------
__device__ __forceinline__ ull pk2(float a, float b){
    ull r; asm("mov.b64 %0, {%1,%2};" : "=l"(r) : "f"(a), "f"(b)); return r;
}
__device__ __forceinline__ void fma2(ull& d, ull a, ull b){
    asm("fma.rn.f32x2 %0, %1, %2, %3;" : "=l"(d) : "l"(a), "l"(b), "l"(d));
}
__device__ __forceinline__ void add2(ull& d, ull a){
    asm("add.rn.f32x2 %0, %1, %2;" : "=l"(d) : "l"(d), "l"(a));
}
__device__ __forceinline__ float2 up2(ull v){
    float2 r; asm("mov.b64 {%0,%1}, %2;" : "=f"(r.x), "=f"(r.y) : "l"(v)); return r;
}

__device__ __forceinline__ float sigf(float x){
    return __fdividef(1.f, 1.f + __expf(-x));
}
__device__ __forceinline__ float tanhfast(float x){
    float e = __expf(-2.f * fabsf(x));
    float t = __fdividef(1.f - e, 1.f + e);
    return copysignf(t, x);
}

// ---------------- weight pack pre-pass -------------------------------------
__global__ void pack_kernel(const float* __restrict__ w_ih, const float* __restrict__ w_hh,
                            const float* __restrict__ w1,   const float* __restrict__ wu1){
    int idx = blockIdx.x * blockDim.x + threadIdx.x;   // 0..16383
    int k = idx >> 7, j = idx & 127;
    g_packA[idx] = make_float4(w_hh[j*H_ + k], w_hh[(j+H_)*H_ + k],
                               w_hh[(j+2*H_)*H_ + k], w1[j*H_ + k]);
    if (j < 64)  g_wu1T[k*64 + j] = wu1[j*H_ + k];
    if (k < 12)  g_packI[k*H_ + j] = make_float4(w_ih[j*12 + k], w_ih[(j+H_)*12 + k],
                                                 w_ih[(j+2*H_)*12 + k], 0.f);
}

// ---------------- dynamic smem layout (float offsets) -----------------------
#define OFF_H     0        // sh_h  [128][8]  h(t-1) undecayed
#define OFF_HD    1024     // sh_hd [128][8]  gamma_h * h(t-1)
#define OFF_GIN   2048     // sh_gin[12][8]
#define OFF_DT    2144     // sh_dt [8]
#define OFF_HID1  2152     // sh_hid1[8][128]
#define OFF_HIDU  3176     // sh_hidu[8][64]
#define OFF_WU1   3688     // s_wu1 [128][64]
#define OFF_PI    11880    // s_pI  [12][128] float4
#define OFF_PART  18024    // s_part: 24 slots x 128 j, ull each (6144 floats)
#define OFF_WA    24168    // s_wA  [KC][128] float4 (KC*512 floats)
#define SMEM_FLOATS (OFF_WA + KC*H_*4)
#define SMEM_BYTES  (SMEM_FLOATS * 4)   // 194,976 B

// main k-loop body: accumulates 4 gate GEMVs + pred head + unc head
#define KBODY(W4EXPR, KK) do {                                                 \
    float4 wA = (W4EXPR);                                                      \
    ulonglong2 dA = *(const ulonglong2*)(sh_hd + (KK)*8);                      \
    ulonglong2 dB = *(const ulonglong2*)(sh_hd + (KK)*8 + 4);                  \
    ulonglong2 hA = *(const ulonglong2*)(sh_h  + (KK)*8);                      \
    ulonglong2 hB = *(const ulonglong2*)(sh_h  + (KK)*8 + 4);                  \
    ull wr = pk2(wA.x, wA.x), wz = pk2(wA.y, wA.y);                            \
    ull wn = pk2(wA.z, wA.z), wp = pk2(wA.w, wA.w);                            \
    fma2(aR[0],dA.x,wr);  fma2(aR[1],dA.y,wr);  fma2(aR[2],dB.x,wr);  fma2(aR[3],dB.y,wr);  \
    fma2(aZ[0],dA.x,wz);  fma2(aZ[1],dA.y,wz);  fma2(aZ[2],dB.x,wz);  fma2(aZ[3],dB.y,wz);  \
    fma2(aGN[0],dA.x,wn); fma2(aGN[1],dA.y,wn); fma2(aGN[2],dB.x,wn); fma2(aGN[3],dB.y,wn); \
    fma2(aP[0],hA.x,wp);  fma2(aP[1],hA.y,wp);  fma2(aP[2],hB.x,wp);  fma2(aP[3],hB.y,wp);  \
    if (j < 64) {                                                              \
        float wu = s_wu1[(KK)*64 + j];                                         \
        ull wup = pk2(wu, wu);                                                 \
        fma2(aU[0],hA.x,wup); fma2(aU[1],hA.y,wup);                            \
        fma2(aU[2],hB.x,wup); fma2(aU[3],hB.y,wup);                            \
    }                                                                          \
} while (0)

__global__ void __launch_bounds__(256, 1) grud_kernel(
    const float* __restrict__ x,
    const float* __restrict__ x_mean,
    const float* __restrict__ dxw, const float* __restrict__ dxb,
    const float* __restrict__ dhw, const float* __restrict__ dhb,
    const float* __restrict__ b_ih, const float* __restrict__ b_hh,
    const float* __restrict__ b1,
    const float* __restrict__ w2,  const float* __restrict__ b2,
    const float* __restrict__ bu1,
    const float* __restrict__ wu2, const float* __restrict__ bu2,
    float* __restrict__ out)
{
    extern __shared__ float smem[];
    float*  sh_h   = smem + OFF_H;      // [k*8 + b]
    float*  sh_hd  = smem + OFF_HD;
    float*  sh_gin = smem + OFF_GIN;    // [k*8 + b]
    float*  sh_dt  = smem + OFF_DT;
    float*  sh_hid1= smem + OFF_HID1;   // [b*128 + j]
    float*  sh_hidu= smem + OFF_HIDU;   // [b*64 + j]
    float*  s_wu1  = smem + OFF_WU1;    // [k*64 + j]
    float4* s_pI   = (float4*)(smem + OFF_PI);   // [k*128 + j]
    ull*    s_part = (ull*)  (smem + OFF_PART);  // [(half*12 + a*2+i)*128 + j]
    float4* s_wA   = (float4*)(smem + OFF_WA);   // [k*128 + j], k < KC

    const int tid  = threadIdx.x;
    const int half = tid >> 7;          // warpgroup: 0 -> k[0,64), 1 -> k[64,128)
    const int j    = tid & 127;
    const int b0   = blockIdx.x * BPC;
    const int oth  = 1 - half;

    // stage weights into shared (once)
    for (int i = tid; i < H_*64; i += 256) s_wu1[i] = g_wu1T[i];
    for (int i = tid; i < 12*H_; i += 256) s_pI[i]  = g_packI[i];
    for (int i = tid; i < KC*H_; i += 256) s_wA[i]  = g_packA[i];

    // per-hidden-unit constants
    const float bihr = b_ih[j], bihz = b_ih[H_ + j], bihn = b_ih[2*H_ + j];
    const float bhhr = b_hh[j], bhhz = b_hh[H_ + j], bhhn = b_hh[2*H_ + j];
    const float b1j  = b1[j];
    const float bu1j = (j < 64) ? bu1[j] : 0.f;
    const float dhwj = dhw[j],  dhbj = dhb[j];

    // phase-A (imputation) constants: tid<48 -> (batch ab, feature ac)
    const int ab = tid / 6, ac = tid - ab * 6;
    float xm = 0.f, axw = 0.f, axb = 0.f, b2c = 0.f;
    if (tid < 48) { xm = x_mean[ac]; axw = dxw[ac]; axb = dxb[ac]; b2c = b2[ac]; }
    // unc reducer constants: tid in [128,176) -> (ub, uc)
    const int ui = tid - 128;
    const int ub = ui / 6, uc = ui - ub * 6;
    float bu2c = 0.f;
    if (ui >= 0 && ui < 48) bu2c = bu2[uc];

    float running = 0.f, xlast = 0.f;
    float h_reg[4];                      // this thread's 4 batches: gb = half*4 + lb
    #pragma unroll
    for (int lb = 0; lb < 4; lb++) h_reg[lb] = 0.f;

    __syncthreads();   // staged weights ready

    for (int t = 0; t <= T_; ++t) {
        // ---------------- Phase A: impute inputs for step t -----------------
        if (t < T_ && tid < 48) {
            const float* xp = x + ((size_t)(b0 + ab) * T_ + t) * 13;
            float xv  = xp[ac];
            float mm  = xp[6 + ac];
            float dtv = xp[12];
            bool obs = (mm > 0.5f);
            running = obs ? 0.f : (running + dtv);
            float gx = __expf(-fmaxf(running * axw + axb, 0.f));
            xlast = obs ? xv : xlast;
            float xhat = mm * xv + (1.f - mm) * (gx * xlast + (1.f - gx) * xm);
            sh_gin[ac * 8 + ab]       = xhat;
            sh_gin[(6 + ac) * 8 + ab] = mm;
            if (ac == 0) sh_dt[ab] = dtv;
        }
        __syncthreads();   // bar1: gin/dt ready

        // ---------------- Phase B: decay own 4 batches, publish -------------
        float hdec[4];
        #pragma unroll
        for (int lb = 0; lb < 4; lb++) {
            float g = __expf(-fmaxf(sh_dt[half*4 + lb] * dhwj + dhbj, 0.f));
            hdec[lb] = h_reg[lb] * g;
        }
        *(float4*)(sh_h  + j*8 + half*4) = make_float4(h_reg[0], h_reg[1], h_reg[2], h_reg[3]);
        *(float4*)(sh_hd + j*8 + half*4) = make_float4(hdec[0], hdec[1], hdec[2], hdec[3]);
        __syncthreads();   // bar2: h/hd published

        // ---------------- Phase C: k-split fused GEMV loops -----------------
        ull aR[4], aZ[4], aGN[4], aIN[4], aP[4], aU[4];
        #pragma unroll
        for (int p = 0; p < 4; p++) { aR[p]=0; aZ[p]=0; aGN[p]=0; aIN[p]=0; aP[p]=0; aU[p]=0; }

        // input-to-hidden (12 k, split 6/6)
        {
            int kin0 = half * 6;
            #pragma unroll
            for (int kk = 0; kk < 6; kk++) {
                int k = kin0 + kk;
                float4 wi = s_pI[k*H_ + j];
                ull wr = pk2(wi.x, wi.x), wz = pk2(wi.y, wi.y), wn = pk2(wi.z, wi.z);
                ulonglong2 gA = *(const ulonglong2*)(sh_gin + k*8);
                ulonglong2 gB = *(const ulonglong2*)(sh_gin + k*8 + 4);
                fma2(aR[0], gA.x, wr); fma2(aR[1], gA.y, wr); fma2(aR[2], gB.x, wr); fma2(aR[3], gB.y, wr);
                fma2(aZ[0], gA.x, wz); fma2(aZ[1], gA.y, wz); fma2(aZ[2], gB.x, wz); fma2(aZ[3], gB.y, wz);
                fma2(aIN[0],gA.x, wn); fma2(aIN[1],gA.y, wn); fma2(aIN[2],gB.x, wn); fma2(aIN[3],gB.y, wn);
            }
        }

        // hidden-to-hidden + heads over this half's k range
        if (half == 0) {
            #pragma unroll 4
            for (int k = 0; k < KC; k++)  KBODY(s_wA[k*H_ + j], k);
            #pragma unroll 4
            for (int k = KC; k < 64; k++) KBODY(g_packA[k*H_ + j], k);
        } else {
            #pragma unroll 4
            for (int k = 64; k < H_; k++) KBODY(g_packA[k*H_ + j], k);
        }

        // ---------------- Phase C': exchange partial sums -------------------
        // write the 2 batch-pairs this thread does NOT own (other half's batches)
        {
            int fp = oth * 2;   // foreign pair base
            ull* wslot = s_part + (size_t)(half*12)*128 + j;
            wslot[0*128]  = aR[fp];   wslot[1*128]  = aR[fp+1];
            wslot[2*128]  = aZ[fp];   wslot[3*128]  = aZ[fp+1];
            wslot[4*128]  = aGN[fp];  wslot[5*128]  = aGN[fp+1];
            wslot[6*128]  = aIN[fp];  wslot[7*128]  = aIN[fp+1];
            wslot[8*128]  = aP[fp];   wslot[9*128]  = aP[fp+1];
            wslot[10*128] = aU[fp];   wslot[11*128] = aU[fp+1];
        }
        __syncthreads();   // bar3: partials exchanged
        {
            int op = half * 2;  // own pair base
            const ull* rslot = s_part + (size_t)(oth*12)*128 + j;
            add2(aR[op],  rslot[0*128]);  add2(aR[op+1],  rslot[1*128]);
            add2(aZ[op],  rslot[2*128]);  add2(aZ[op+1],  rslot[3*128]);
            add2(aGN[op], rslot[4*128]);  add2(aGN[op+1], rslot[5*128]);
            add2(aIN[op], rslot[6*128]);  add2(aIN[op+1], rslot[7*128]);
            add2(aP[op],  rslot[8*128]);  add2(aP[op+1],  rslot[9*128]);
            add2(aU[op],  rslot[10*128]); add2(aU[op+1],  rslot[11*128]);
        }

        // ---------------- Phase D: gates + head activations (own 4 batches) -
        {
            int op = half * 2;
            float fR[4], fZ[4], fGN[4], fIN[4], fP[4], fU[4];
            float2 v;
            v = up2(aR[op]);    fR[0]=v.x;  fR[1]=v.y;
            v = up2(aR[op+1]);  fR[2]=v.x;  fR[3]=v.y;
            v = up2(aZ[op]);    fZ[0]=v.x;  fZ[1]=v.y;
            v = up2(aZ[op+1]);  fZ[2]=v.x;  fZ[3]=v.y;
            v = up2(aGN[op]);   fGN[0]=v.x; fGN[1]=v.y;
            v = up2(aGN[op+1]); fGN[2]=v.x; fGN[3]=v.y;
            v = up2(aIN[op]);   fIN[0]=v.x; fIN[1]=v.y;
            v = up2(aIN[op+1]); fIN[2]=v.x; fIN[3]=v.y;
            v = up2(aP[op]);    fP[0]=v.x;  fP[1]=v.y;
            v = up2(aP[op+1]);  fP[2]=v.x;  fP[3]=v.y;
            v = up2(aU[op]);    fU[0]=v.x;  fU[1]=v.y;
            v = up2(aU[op+1]);  fU[2]=v.x;  fU[3]=v.y;

            #pragma unroll
            for (int lb = 0; lb < 4; lb++) {
                int gb = half*4 + lb;
                float r = sigf(fR[lb] + bihr + bhhr);
                float z = sigf(fZ[lb] + bihz + bhhz);
                float n = tanhfast(fIN[lb] + bihn + r * (fGN[lb] + bhhn));
                h_reg[lb] = n + z * (hdec[lb] - n);          // (1-z)*n + z*h_dec
                // heads for step t-1 (aP/aU built from sh_h = h(t-1))
                sh_hid1[gb*H_ + j] = fmaxf(fP[lb] + b1j, 0.f);
                if (j < 64) sh_hidu[gb*64 + j] = fmaxf(fU[lb] + bu1j, 0.f);
            }
        }
        __syncthreads();   // bar4: hid1/hidu ready

        // ---------------- Reduction: head layer-2, write outputs t-1 --------
        if (t >= 1) {
            if (tid < 48) {              // pred head (half 0)
                float acc = b2c;
                const float* wrow = w2 + ac * H_;
                #pragma unroll 8
                for (int k = 0; k < H_; k += 4) {
                    float4 hh = *(const float4*)(sh_hid1 + ab*H_ + k);
                    float4 ww = *(const float4*)(wrow + k);
                    acc += hh.x*ww.x + hh.y*ww.y + hh.z*ww.z + hh.w*ww.w;
                }
                out[((size_t)(b0 + ab) * T_ + (t - 1)) * C_ + ac] = acc;
            } else if (ui >= 0 && ui < 48) {   // unc head (half 1)
                float acc = bu2c;
                const float* wrow = wu2 + uc * 64;
                #pragma unroll 8
                for (int k = 0; k < 64; k += 4) {
                    float4 hh = *(const float4*)(sh_hidu + ub*64 + k);
                    float4 ww = *(const float4*)(wrow + k);
                    acc += hh.x*ww.x + hh.y*ww.y + hh.z*ww.z + hh.w*ww.w;
                }
                float sp = fmaxf(acc, 0.f) + log1pf(__expf(-fabsf(acc)));  // softplus
                out[(size_t)B_*T_*C_ + ((size_t)(b0 + ub) * T_ + (t - 1)) * C_ + uc] = sp;
            }
        }
        // Next Phase-A writes sh_gin/sh_dt (disjoint from sh_hid1/hidu read
        // here); next Phase-B overwrite of sh_h/sh_hd is fenced by bar1.
    }
}

extern "C" void kernel_launch(void* const* d_in, const int* in_sizes, int n_in,
                              void* d_out, int out_size) {
    const float* x      = (const float*)d_in[0];
    const float* x_mean = (const float*)d_in[1];
    const float* dxw    = (const float*)d_in[2];
    const float* dxb    = (const float*)d_in[3];
    const float* dhw    = (const float*)d_in[4];
    const float* dhb    = (const float*)d_in[5];
    const float* w_ih   = (const float*)d_in[6];
    const float* w_hh   = (const float*)d_in[7];
    const float* b_ih   = (const float*)d_in[8];
    const float* b_hh   = (const float*)d_in[9];
    const float* w1     = (const float*)d_in[10];
    const float* b1     = (const float*)d_in[11];
    const float* w2     = (const float*)d_in[12];
    const float* b2     = (const float*)d_in[13];
    const float* wu1    = (const float*)d_in[14];
    const float* bu1    = (const float*)d_in[15];
    const float* wu2    = (const float*)d_in[16];
    const float* bu2    = (const float*)d_in[17];
    float* out = (float*)d_out;

    // idempotent, not stream-captured; no static guards (harness forbids them)
    cudaFuncSetAttribute(grud_kernel, cudaFuncAttributeMaxDynamicSharedMemorySize, SMEM_BYTES);

    pack_kernel<<<NCTA, 128>>>(w_ih, w_hh, w1, wu1);
    grud_kernel<<<NCTA, 256, SMEM_BYTES>>>(x, x_mean, dxw, dxb, dhw, dhb,
                                           b_ih, b_hh, b1, w2, b2, bu1, wu2, bu2, out);
}